// round 1
// baseline (speedup 1.0000x reference)
#include <cuda_runtime.h>
#include <cuda_bf16.h>
#include <math.h>

// Problem constants
#define Hh 16
#define HS 64
#define E  1024
#define Tt 2048
#define Bb 4
#define PF 4
#define BT (Bb*Tt)          // 8192
#define E3 (3*E)            // 3072
#define FE (PF*E)           // 4096

// ---------------- scratch (device globals; no allocation allowed) -----------
__device__ float g_h   [BT * E];      // LN output / attn-out / LN2 output (reused)
__device__ float g_qkv [BT * E3];     // packed q,k,v rows: [b*T+t][{q,k,v}*1024 + h*64 + d]
__device__ float g_x1  [BT * E];      // x + attn proj (residual stream)
__device__ float g_ff1 [BT * FE];     // relu(h2@W1+b1)
__device__ float g_wqkv[E * E3];      // packed weights [e][{q,k,v}*1024 + h*64 + d]

// ---------------- LayerNorm (torch unbiased var, eps inside sqrt) -----------
__device__ __forceinline__ float block_sum_256(float v, float* red) {
    #pragma unroll
    for (int o = 16; o > 0; o >>= 1) v += __shfl_xor_sync(0xffffffffu, v, o);
    int lane = threadIdx.x & 31, w = threadIdx.x >> 5;
    if (lane == 0) red[w] = v;
    __syncthreads();
    float r = (threadIdx.x < 8) ? red[threadIdx.x] : 0.f;
    if (w == 0) {
        #pragma unroll
        for (int o = 4; o > 0; o >>= 1) r += __shfl_xor_sync(0xffu, r, o);
        if (lane == 0) red[0] = r;
    }
    __syncthreads();
    float out = red[0];
    __syncthreads();
    return out;
}

__global__ void ln_kernel(const float* __restrict__ x, const float* __restrict__ gain,
                          const float* __restrict__ bias, float* __restrict__ o) {
    __shared__ float red[8];
    long row = blockIdx.x;
    const float4* xr = (const float4*)(x + row * E);
    int tid = threadIdx.x;                   // 256 threads, 4 elems each
    float4 v = xr[tid];
    float s = v.x + v.y + v.z + v.w;
    float mean = block_sum_256(s, red) * (1.0f / E);
    float dx = v.x - mean, dy = v.y - mean, dz = v.z - mean, dw = v.w - mean;
    float sq = dx*dx + dy*dy + dz*dz + dw*dw;
    float var = block_sum_256(sq, red) * (1.0f / (E - 1));
    float inv = 1.0f / sqrtf(var + 1e-5f);
    float4 g = ((const float4*)gain)[tid];
    float4 b = ((const float4*)bias)[tid];
    float4 r;
    r.x = dx * inv * g.x + b.x;
    r.y = dy * inv * g.y + b.y;
    r.z = dz * inv * g.z + b.z;
    r.w = dw * inv * g.w + b.w;
    ((float4*)(o + row * E))[tid] = r;
}

// ---------------- pack Wq/Wk/Wv [H,E,HS] -> [E, 3*H*HS] ---------------------
__global__ void pack_wqkv(const float* __restrict__ Wq, const float* __restrict__ Wk,
                          const float* __restrict__ Wv, float* __restrict__ out) {
    int idx = blockIdx.x * 256 + threadIdx.x;
    if (idx >= E * E3) return;
    int n = idx % E3, e = idx / E3;
    int s = n >> 10, r = n & 1023, h = r >> 6, d = r & 63;
    const float* W = (s == 0) ? Wq : (s == 1) ? Wk : Wv;
    out[idx] = W[h * (E * HS) + e * HS + d];
}

// ---------------- generic 128x128x8 SGEMM with epilogue ---------------------
// MODE 0: C = A@B
// MODE 1: C = A@B + bias[n] + res[m,n]
// MODE 2: C = relu(A@B + bias[n])
template<int MODE>
__global__ __launch_bounds__(256) void sgemm128(
    const float* __restrict__ A, const float* __restrict__ B,
    const float* __restrict__ bias, const float* __restrict__ res,
    float* __restrict__ C, int M, int N, int K)
{
    __shared__ float As[8][128];
    __shared__ float Bs[8][128];
    int tid = threadIdx.x;
    int tx = tid & 15, ty = tid >> 4;
    int bx = blockIdx.x, by = blockIdx.y;

    const float* Aptr = A + (long)(by * 128) * K;
    const float* Bptr = B + bx * 128;

    int a_r = tid >> 1,  a_c = (tid & 1) * 4;     // A: 128 rows x 8 k
    int b_r = tid >> 5,  b_c = (tid & 31) * 4;    // B: 8 k x 128 cols

    float acc[8][8];
    #pragma unroll
    for (int i = 0; i < 8; i++)
        #pragma unroll
        for (int j = 0; j < 8; j++) acc[i][j] = 0.f;

    for (int k0 = 0; k0 < K; k0 += 8) {
        float4 av = *(const float4*)(Aptr + (long)a_r * K + k0 + a_c);
        As[a_c + 0][a_r] = av.x;
        As[a_c + 1][a_r] = av.y;
        As[a_c + 2][a_r] = av.z;
        As[a_c + 3][a_r] = av.w;
        float4 bv = *(const float4*)(Bptr + (long)(k0 + b_r) * N + b_c);
        *(float4*)&Bs[b_r][b_c] = bv;
        __syncthreads();
        #pragma unroll
        for (int kk = 0; kk < 8; kk++) {
            float4 a0 = *(const float4*)&As[kk][ty * 8];
            float4 a1 = *(const float4*)&As[kk][ty * 8 + 4];
            float4 b0 = *(const float4*)&Bs[kk][tx * 8];
            float4 b1 = *(const float4*)&Bs[kk][tx * 8 + 4];
            float ar[8] = {a0.x, a0.y, a0.z, a0.w, a1.x, a1.y, a1.z, a1.w};
            float br[8] = {b0.x, b0.y, b0.z, b0.w, b1.x, b1.y, b1.z, b1.w};
            #pragma unroll
            for (int i = 0; i < 8; i++)
                #pragma unroll
                for (int j = 0; j < 8; j++)
                    acc[i][j] = fmaf(ar[i], br[j], acc[i][j]);
        }
        __syncthreads();
    }

    int row0 = by * 128 + ty * 8;
    int col0 = bx * 128 + tx * 8;
    #pragma unroll
    for (int i = 0; i < 8; i++) {
        long roff = (long)(row0 + i) * N + col0;
        #pragma unroll
        for (int j4 = 0; j4 < 2; j4++) {
            float4 v;
            v.x = acc[i][j4 * 4 + 0];
            v.y = acc[i][j4 * 4 + 1];
            v.z = acc[i][j4 * 4 + 2];
            v.w = acc[i][j4 * 4 + 3];
            if (MODE == 1 || MODE == 2) {
                float4 bvec = *(const float4*)(bias + col0 + j4 * 4);
                v.x += bvec.x; v.y += bvec.y; v.z += bvec.z; v.w += bvec.w;
            }
            if (MODE == 1) {
                float4 rv = *(const float4*)(res + roff + j4 * 4);
                v.x += rv.x; v.y += rv.y; v.z += rv.z; v.w += rv.w;
            }
            if (MODE == 2) {
                v.x = fmaxf(v.x, 0.f); v.y = fmaxf(v.y, 0.f);
                v.z = fmaxf(v.z, 0.f); v.w = fmaxf(v.w, 0.f);
            }
            *(float4*)(C + roff + j4 * 4) = v;
        }
    }
}

// ---------------- causal flash attention (fp32) ------------------------------
// grid: (T/64, B*H), block: 64 threads, one query row per thread.
// Reads q,k,v strided out of g_qkv; writes output in concat-head [B,T,E] layout.
__global__ __launch_bounds__(64) void attn_kernel(const float* __restrict__ qkv,
                                                  float* __restrict__ out) {
    __shared__ float Ksh[64 * 64];
    __shared__ float Vsh[64 * 64];
    int tidx = threadIdx.x;
    int qtile = blockIdx.x;
    int bh = blockIdx.y;
    int b = bh >> 4, h = bh & 15;
    int t = qtile * 64 + tidx;

    const float* base = qkv + (long)b * Tt * E3 + h * HS;
    const float4* qrow = (const float4*)(base + (long)t * E3);
    float4 q[16];
    #pragma unroll
    for (int i = 0; i < 16; i++) q[i] = qrow[i];

    float acc[64];
    #pragma unroll
    for (int d = 0; d < 64; d++) acc[d] = 0.f;
    float m = -INFINITY, l = 0.f;

    for (int j = 0; j <= qtile; j++) {
        const float* kbase = base + (long)(j * 64) * E3 + E;      // k block
        const float* vbase = base + (long)(j * 64) * E3 + 2 * E;  // v block
        #pragma unroll 4
        for (int i = 0; i < 64; i++) {
            Ksh[i * 64 + tidx] = kbase[(long)i * E3 + tidx];
            Vsh[i * 64 + tidx] = vbase[(long)i * E3 + tidx];
        }
        __syncthreads();

        int kmax = t - j * 64 + 1;  // number of unmasked keys in this tile (may exceed 64)
        #pragma unroll 1
        for (int kk = 0; kk < 64; kk++) {
            if (kk < kmax) {
                const float4* kr = (const float4*)&Ksh[kk * 64];
                float s = 0.f;
                #pragma unroll
                for (int i = 0; i < 16; i++) {
                    float4 kv = kr[i];
                    s = fmaf(q[i].x, kv.x, s);
                    s = fmaf(q[i].y, kv.y, s);
                    s = fmaf(q[i].z, kv.z, s);
                    s = fmaf(q[i].w, kv.w, s);
                }
                s *= 8.0f;  // * hs**0.5 (faithful to source)
                const float* vr = &Vsh[kk * 64];
                if (s > m) {
                    float corr = __expf(m - s);
                    m = s;
                    l = l * corr + 1.0f;
                    #pragma unroll
                    for (int d = 0; d < 64; d++)
                        acc[d] = fmaf(acc[d], corr, vr[d]);
                } else {
                    float p = __expf(s - m);
                    l += p;
                    #pragma unroll
                    for (int d = 0; d < 64; d++)
                        acc[d] = fmaf(p, vr[d], acc[d]);
                }
            }
        }
        __syncthreads();
    }

    float inv = 1.0f / l;
    float* orow = out + ((long)b * Tt + t) * E + h * HS;
    #pragma unroll
    for (int d = 0; d < 64; d++) orow[d] = acc[d] * inv;
}

// ---------------- launch ------------------------------------------------------
extern "C" void kernel_launch(void* const* d_in, const int* in_sizes, int n_in,
                              void* d_out, int out_size) {
    const float* x   = (const float*)d_in[0];
    const float* Wq  = (const float*)d_in[1];
    const float* Wk  = (const float*)d_in[2];
    const float* Wv  = (const float*)d_in[3];
    const float* Wp  = (const float*)d_in[4];
    const float* bp  = (const float*)d_in[5];
    const float* W1  = (const float*)d_in[6];
    const float* b1  = (const float*)d_in[7];
    const float* W2  = (const float*)d_in[8];
    const float* b2  = (const float*)d_in[9];
    const float* g1  = (const float*)d_in[10];
    const float* be1 = (const float*)d_in[11];
    const float* g2  = (const float*)d_in[12];
    const float* be2 = (const float*)d_in[13];
    float* out = (float*)d_out;

    float *ph, *pqkv, *px1, *pff1, *pwqkv;
    cudaGetSymbolAddress((void**)&ph,    g_h);
    cudaGetSymbolAddress((void**)&pqkv,  g_qkv);
    cudaGetSymbolAddress((void**)&px1,   g_x1);
    cudaGetSymbolAddress((void**)&pff1,  g_ff1);
    cudaGetSymbolAddress((void**)&pwqkv, g_wqkv);

    // 1. pack qkv weights: [H,E,HS]x3 -> [E, 3072]
    pack_wqkv<<<(E * E3 + 255) / 256, 256>>>(Wq, Wk, Wv, pwqkv);

    // 2. h = LN1(x)
    ln_kernel<<<BT, 256>>>(x, g1, be1, ph);

    // 3. qkv = h @ Wqkv   [8192,1024] x [1024,3072]
    sgemm128<0><<<dim3(E3 / 128, BT / 128), 256>>>(ph, pwqkv, nullptr, nullptr,
                                                   pqkv, BT, E3, E);

    // 4. attention -> concat-head output into g_h (reused)
    attn_kernel<<<dim3(Tt / 64, Bb * Hh), 64>>>(pqkv, ph);

    // 5. x1 = x + attn_out @ Wp + bp
    sgemm128<1><<<dim3(E / 128, BT / 128), 256>>>(ph, Wp, bp, x, px1, BT, E, E);

    // 6. h2 = LN2(x1) -> g_h (reused)
    ln_kernel<<<BT, 256>>>(px1, g2, be2, ph);

    // 7. ff1 = relu(h2 @ W1 + b1)
    sgemm128<2><<<dim3(FE / 128, BT / 128), 256>>>(ph, W1, b1, nullptr, pff1, BT, FE, E);

    // 8. out = x1 + ff1 @ W2 + b2
    sgemm128<1><<<dim3(E / 128, BT / 128), 256>>>(pff1, W2, b2, px1, out, BT, E, FE);
}

// round 2
// speedup vs baseline: 1.2479x; 1.2479x over previous
#include <cuda_runtime.h>
#include <cuda_bf16.h>
#include <math.h>

// Problem constants
#define Hh 16
#define HS 64
#define E  1024
#define Tt 2048
#define Bb 4
#define PF 4
#define BT (Bb*Tt)          // 8192
#define E3 (3*E)            // 3072
#define FE (PF*E)           // 4096

// ---------------- scratch (device globals; no allocation allowed) -----------
__device__ float g_h   [BT * E];      // LN output / attn-out / LN2 output (reused)
__device__ float g_qkv [BT * E3];     // packed q,k,v rows
__device__ float g_x1  [BT * E];      // x + attn proj (residual stream)
__device__ float g_ff1 [BT * FE];     // relu(h2@W1+b1)
__device__ float g_wqkv[E * E3];      // packed weights [e][{q,k,v}*1024 + h*64 + d]

// ---------------- LayerNorm (torch unbiased var, eps inside sqrt) -----------
__device__ __forceinline__ float block_sum_256(float v, float* red) {
    #pragma unroll
    for (int o = 16; o > 0; o >>= 1) v += __shfl_xor_sync(0xffffffffu, v, o);
    int lane = threadIdx.x & 31, w = threadIdx.x >> 5;
    if (lane == 0) red[w] = v;
    __syncthreads();
    float r = (threadIdx.x < 8) ? red[threadIdx.x] : 0.f;
    if (w == 0) {
        #pragma unroll
        for (int o = 4; o > 0; o >>= 1) r += __shfl_xor_sync(0xffu, r, o);
        if (lane == 0) red[0] = r;
    }
    __syncthreads();
    float out = red[0];
    __syncthreads();
    return out;
}

__global__ void ln_kernel(const float* __restrict__ x, const float* __restrict__ gain,
                          const float* __restrict__ bias, float* __restrict__ o) {
    __shared__ float red[8];
    long row = blockIdx.x;
    const float4* xr = (const float4*)(x + row * E);
    int tid = threadIdx.x;                   // 256 threads, 4 elems each
    float4 v = xr[tid];
    float s = v.x + v.y + v.z + v.w;
    float mean = block_sum_256(s, red) * (1.0f / E);
    float dx = v.x - mean, dy = v.y - mean, dz = v.z - mean, dw = v.w - mean;
    float sq = dx*dx + dy*dy + dz*dz + dw*dw;
    float var = block_sum_256(sq, red) * (1.0f / (E - 1));
    float inv = 1.0f / sqrtf(var + 1e-5f);
    float4 g = ((const float4*)gain)[tid];
    float4 b = ((const float4*)bias)[tid];
    float4 r;
    r.x = dx * inv * g.x + b.x;
    r.y = dy * inv * g.y + b.y;
    r.z = dz * inv * g.z + b.z;
    r.w = dw * inv * g.w + b.w;
    ((float4*)(o + row * E))[tid] = r;
}

// ---------------- pack Wq/Wk/Wv [H,E,HS] -> [E, 3*H*HS] ---------------------
__global__ void pack_wqkv(const float* __restrict__ Wq, const float* __restrict__ Wk,
                          const float* __restrict__ Wv, float* __restrict__ out) {
    int idx = blockIdx.x * 256 + threadIdx.x;
    if (idx >= E * E3) return;
    int n = idx % E3, e = idx / E3;
    int s = n >> 10, r = n & 1023, h = r >> 6, d = r & 63;
    const float* W = (s == 0) ? Wq : (s == 1) ? Wk : Wv;
    out[idx] = W[h * (E * HS) + e * HS + d];
}

// ================= TF32 tensor-core GEMM (mma.sync m16n8k8) =================
// Block tile 128x128, K-stage 16, double-buffered, fragment-permuted smem.
// 8 warps: warp_m = wid&1 (64 rows), warp_n = wid>>1 (32 cols).
// MODE 0: C = A@B ; MODE 1: C = A@B + bias + res ; MODE 2: C = relu(A@B + bias)

__device__ __forceinline__ unsigned f2tf32(float x) {
    unsigned u;
    asm("cvt.rna.tf32.f32 %0, %1;" : "=r"(u) : "f"(x));
    return u;
}

// scatter one A float4 (tile row ar, cols ac4*4..+3) into permuted layout
__device__ __forceinline__ void stageA(unsigned* As, int f, float4 v) {
    int ar = f >> 2, ac4 = f & 3;
    int rr = ar & 15, mt = ar >> 4;
    float vals[4] = {v.x, v.y, v.z, v.w};
    #pragma unroll
    for (int e = 0; e < 4; e++) {
        int c = ac4 * 4 + e;
        int ks = c >> 3;
        int slot = ((rr >> 3) & 1) + (((c & 7) >= 4) ? 2 : 0);
        int ln = (rr & 7) * 4 + (c & 3);
        As[((((mt << 1) + ks) << 5) + ln) * 4 + slot] = f2tf32(vals[e]);
    }
}

// scatter one B float4 (tile k-row kr, cols nc4*4..+3)
__device__ __forceinline__ void stageB(unsigned* Bs, int f, float4 v) {
    int kr = f >> 5, nc4 = f & 31;
    int ks = kr >> 3, krr = kr & 7;
    int slot = krr >> 2;
    float vals[4] = {v.x, v.y, v.z, v.w};
    #pragma unroll
    for (int e = 0; e < 4; e++) {
        int n = nc4 * 4 + e;
        int ln = (n & 7) * 4 + (krr & 3);
        int nt = n >> 3;
        Bs[((((nt << 1) + ks) << 5) + ln) * 2 + slot] = f2tf32(vals[e]);
    }
}

#define MMA_TF32(c, a, b)                                                         \
    asm volatile("mma.sync.aligned.m16n8k8.row.col.f32.tf32.tf32.f32 "            \
                 "{%0,%1,%2,%3},{%4,%5,%6,%7},{%8,%9},{%0,%1,%2,%3};"             \
                 : "+f"(c[0]), "+f"(c[1]), "+f"(c[2]), "+f"(c[3])                  \
                 : "r"(a.x), "r"(a.y), "r"(a.z), "r"(a.w), "r"(b.x), "r"(b.y))

template<int MODE>
__global__ __launch_bounds__(256, 2) void tgemm128(
    const float* __restrict__ A, const float* __restrict__ B,
    const float* __restrict__ bias, const float* __restrict__ res,
    float* __restrict__ C, int M, int N, int K)
{
    // two buffers, each: A 2048 tf32 + B 2048 tf32
    __shared__ unsigned As[2][2048];
    __shared__ unsigned Bs[2][2048];

    int tid = threadIdx.x;
    int ln = tid & 31, wid = tid >> 5;
    int warp_m = wid & 1, warp_n = wid >> 1;
    int bx = blockIdx.x, by = blockIdx.y;

    const float* Aptr = A + (long)(by * 128) * K;
    const float* Bptr = B + bx * 128;

    // staging: each thread owns float4 indices f0,f1 for both A and B tiles
    int f0 = tid * 2, f1 = tid * 2 + 1;
    int a_r0 = f0 >> 2, a_c0 = (f0 & 3) * 4;
    int a_r1 = f1 >> 2, a_c1 = (f1 & 3) * 4;
    int b_k0 = f0 >> 5, b_n0 = (f0 & 31) * 4;
    int b_k1 = f1 >> 5, b_n1 = (f1 & 31) * 4;

    float acc[4][4][4];
    #pragma unroll
    for (int i = 0; i < 4; i++)
        #pragma unroll
        for (int j = 0; j < 4; j++)
            #pragma unroll
            for (int e = 0; e < 4; e++) acc[i][j][e] = 0.f;

    // prologue: stage tile 0
    {
        float4 av0 = *(const float4*)(Aptr + (long)a_r0 * K + a_c0);
        float4 av1 = *(const float4*)(Aptr + (long)a_r1 * K + a_c1);
        float4 bv0 = *(const float4*)(Bptr + (long)b_k0 * N + b_n0);
        float4 bv1 = *(const float4*)(Bptr + (long)b_k1 * N + b_n1);
        stageA(As[0], f0, av0); stageA(As[0], f1, av1);
        stageB(Bs[0], f0, bv0); stageB(Bs[0], f1, bv1);
    }
    __syncthreads();

    int niter = K >> 4;
    for (int it = 0; it < niter; it++) {
        const unsigned* Asb = As[it & 1];
        const unsigned* Bsb = Bs[it & 1];

        float4 av0, av1, bv0, bv1;
        bool has_next = (it + 1) < niter;
        if (has_next) {
            int k0 = (it + 1) << 4;
            av0 = *(const float4*)(Aptr + (long)a_r0 * K + k0 + a_c0);
            av1 = *(const float4*)(Aptr + (long)a_r1 * K + k0 + a_c1);
            bv0 = *(const float4*)(Bptr + (long)(k0 + b_k0) * N + b_n0);
            bv1 = *(const float4*)(Bptr + (long)(k0 + b_k1) * N + b_n1);
        }

        #pragma unroll
        for (int ks = 0; ks < 2; ks++) {
            uint4 af[4];
            uint2 bf[4];
            #pragma unroll
            for (int mt = 0; mt < 4; mt++)
                af[mt] = ((const uint4*)Asb)[(((warp_m * 4 + mt) << 1) + ks) * 32 + ln];
            #pragma unroll
            for (int nt = 0; nt < 4; nt++)
                bf[nt] = ((const uint2*)Bsb)[(((warp_n * 4 + nt) << 1) + ks) * 32 + ln];
            #pragma unroll
            for (int mt = 0; mt < 4; mt++)
                #pragma unroll
                for (int nt = 0; nt < 4; nt++)
                    MMA_TF32(acc[mt][nt], af[mt], bf[nt]);
        }

        if (has_next) {
            unsigned* Asn = As[(it + 1) & 1];
            unsigned* Bsn = Bs[(it + 1) & 1];
            stageA(Asn, f0, av0); stageA(Asn, f1, av1);
            stageB(Bsn, f0, bv0); stageB(Bsn, f1, bv1);
        }
        __syncthreads();
    }

    // epilogue
    int row_base = by * 128 + warp_m * 64;
    int col_base = bx * 128 + warp_n * 32;
    int g = ln >> 2, tg = ln & 3;
    #pragma unroll
    for (int mt = 0; mt < 4; mt++) {
        #pragma unroll
        for (int nt = 0; nt < 4; nt++) {
            int r0 = row_base + mt * 16 + g;
            int c0 = col_base + nt * 8 + tg * 2;
            float2 v0 = make_float2(acc[mt][nt][0], acc[mt][nt][1]);
            float2 v1 = make_float2(acc[mt][nt][2], acc[mt][nt][3]);
            if (MODE == 1 || MODE == 2) {
                float2 bvec = *(const float2*)(bias + c0);
                v0.x += bvec.x; v0.y += bvec.y;
                v1.x += bvec.x; v1.y += bvec.y;
            }
            long off0 = (long)r0 * N + c0;
            long off1 = (long)(r0 + 8) * N + c0;
            if (MODE == 1) {
                float2 r0v = *(const float2*)(res + off0);
                float2 r1v = *(const float2*)(res + off1);
                v0.x += r0v.x; v0.y += r0v.y;
                v1.x += r1v.x; v1.y += r1v.y;
            }
            if (MODE == 2) {
                v0.x = fmaxf(v0.x, 0.f); v0.y = fmaxf(v0.y, 0.f);
                v1.x = fmaxf(v1.x, 0.f); v1.y = fmaxf(v1.y, 0.f);
            }
            *(float2*)(C + off0) = v0;
            *(float2*)(C + off1) = v1;
        }
    }
}

// ---------------- causal flash attention (fp32) ------------------------------
__global__ __launch_bounds__(64) void attn_kernel(const float* __restrict__ qkv,
                                                  float* __restrict__ out) {
    __shared__ float Ksh[64 * 64];
    __shared__ float Vsh[64 * 64];
    int tidx = threadIdx.x;
    int qtile = blockIdx.x;
    int bh = blockIdx.y;
    int b = bh >> 4, h = bh & 15;
    int t = qtile * 64 + tidx;

    const float* base = qkv + (long)b * Tt * E3 + h * HS;
    const float4* qrow = (const float4*)(base + (long)t * E3);
    float4 q[16];
    #pragma unroll
    for (int i = 0; i < 16; i++) q[i] = qrow[i];

    float acc[64];
    #pragma unroll
    for (int d = 0; d < 64; d++) acc[d] = 0.f;
    float m = -INFINITY, l = 0.f;

    for (int j = 0; j <= qtile; j++) {
        const float* kbase = base + (long)(j * 64) * E3 + E;
        const float* vbase = base + (long)(j * 64) * E3 + 2 * E;
        #pragma unroll 4
        for (int i = 0; i < 64; i++) {
            Ksh[i * 64 + tidx] = kbase[(long)i * E3 + tidx];
            Vsh[i * 64 + tidx] = vbase[(long)i * E3 + tidx];
        }
        __syncthreads();

        int kmax = t - j * 64 + 1;
        #pragma unroll 1
        for (int kk = 0; kk < 64; kk++) {
            if (kk < kmax) {
                const float4* kr = (const float4*)&Ksh[kk * 64];
                float s = 0.f;
                #pragma unroll
                for (int i = 0; i < 16; i++) {
                    float4 kv = kr[i];
                    s = fmaf(q[i].x, kv.x, s);
                    s = fmaf(q[i].y, kv.y, s);
                    s = fmaf(q[i].z, kv.z, s);
                    s = fmaf(q[i].w, kv.w, s);
                }
                s *= 8.0f;
                const float* vr = &Vsh[kk * 64];
                if (s > m) {
                    float corr = __expf(m - s);
                    m = s;
                    l = l * corr + 1.0f;
                    #pragma unroll
                    for (int d = 0; d < 64; d++)
                        acc[d] = fmaf(acc[d], corr, vr[d]);
                } else {
                    float p = __expf(s - m);
                    l += p;
                    #pragma unroll
                    for (int d = 0; d < 64; d++)
                        acc[d] = fmaf(p, vr[d], acc[d]);
                }
            }
        }
        __syncthreads();
    }

    float inv = 1.0f / l;
    float* orow = out + ((long)b * Tt + t) * E + h * HS;
    #pragma unroll
    for (int d = 0; d < 64; d++) orow[d] = acc[d] * inv;
}

// ---------------- launch ------------------------------------------------------
extern "C" void kernel_launch(void* const* d_in, const int* in_sizes, int n_in,
                              void* d_out, int out_size) {
    const float* x   = (const float*)d_in[0];
    const float* Wq  = (const float*)d_in[1];
    const float* Wk  = (const float*)d_in[2];
    const float* Wv  = (const float*)d_in[3];
    const float* Wp  = (const float*)d_in[4];
    const float* bp  = (const float*)d_in[5];
    const float* W1  = (const float*)d_in[6];
    const float* b1  = (const float*)d_in[7];
    const float* W2  = (const float*)d_in[8];
    const float* b2  = (const float*)d_in[9];
    const float* g1  = (const float*)d_in[10];
    const float* be1 = (const float*)d_in[11];
    const float* g2  = (const float*)d_in[12];
    const float* be2 = (const float*)d_in[13];
    float* out = (float*)d_out;

    float *ph, *pqkv, *px1, *pff1, *pwqkv;
    cudaGetSymbolAddress((void**)&ph,    g_h);
    cudaGetSymbolAddress((void**)&pqkv,  g_qkv);
    cudaGetSymbolAddress((void**)&px1,   g_x1);
    cudaGetSymbolAddress((void**)&pff1,  g_ff1);
    cudaGetSymbolAddress((void**)&pwqkv, g_wqkv);

    // 1. pack qkv weights
    pack_wqkv<<<(E * E3 + 255) / 256, 256>>>(Wq, Wk, Wv, pwqkv);

    // 2. h = LN1(x)
    ln_kernel<<<BT, 256>>>(x, g1, be1, ph);

    // 3. qkv = h @ Wqkv   [8192,1024] x [1024,3072]
    tgemm128<0><<<dim3(E3 / 128, BT / 128), 256>>>(ph, pwqkv, nullptr, nullptr,
                                                   pqkv, BT, E3, E);

    // 4. attention -> concat-head output into g_h (reused)
    attn_kernel<<<dim3(Tt / 64, Bb * Hh), 64>>>(pqkv, ph);

    // 5. x1 = x + attn_out @ Wp + bp
    tgemm128<1><<<dim3(E / 128, BT / 128), 256>>>(ph, Wp, bp, x, px1, BT, E, E);

    // 6. h2 = LN2(x1)
    ln_kernel<<<BT, 256>>>(px1, g2, be2, ph);

    // 7. ff1 = relu(h2 @ W1 + b1)
    tgemm128<2><<<dim3(FE / 128, BT / 128), 256>>>(ph, W1, b1, nullptr, pff1, BT, FE, E);

    // 8. out = x1 + ff1 @ W2 + b2
    tgemm128<1><<<dim3(E / 128, BT / 128), 256>>>(pff1, W2, b2, px1, out, BT, E, FE);
}